// round 14
// baseline (speedup 1.0000x reference)
#include <cuda_runtime.h>
#include <cuda_fp16.h>
#include <cstdint>

#define E_TOT   30000
#define NB      10
#define WNUM    9216
#define EB      128
#define NTHR    512
#define INV_S3  0.5773502691896258f
#define PW0     0.10206207261596575f
#define PW1     0.17677669529663687f
#define PW1S    (PW1 * INV_S3)

#define NCH 102
#define NSLOT 54

// Packed half2 B fragments (u32 each), fragment-ordered per chunk (same as R10).
__device__ uint32_t g_B1[51 * 1024];   // N=64 chunks: c<34 Wa halves, c>=34 Wd
__device__ uint32_t g_B2[34 * 512];    // N=32 chunks: Wb halves
__device__ uint32_t g_B3[17 * 512];    // N=32 chunks: Wc

// SMEM word offsets (23264 words = 90.9 KB -> 2 CTAs/SM)
#define OFF_H    0        // [17][128] f32
#define OFF_X0H  2176     // [32 vpair][129] half2-words (PB f32 overlay after Wb)
#define OFF_PB   OFF_X0H  // [32][129] f32
#define OFF_XCH  6304     // [3 m][16 upair][129] half2-words
#define OFF_ZADH 12496    // [16 upair][129] half2-words
#define OFF_SH0  14560    // [128]
#define OFF_SH1  14688    // [3][128]
#define OFF_BB   15072    // 4 slots x 2048 words
#define SMEM_FL  23264
#define SMEM_BYTES (SMEM_FL * 4)

__device__ __forceinline__ uint32_t pkh2(float lo, float hi) {
    __half2 h = __floats2half2_rn(lo, hi);
    return *reinterpret_cast<uint32_t*>(&h);
}
__device__ __forceinline__ uint32_t h2bcast(float v) {
    __half2 h = __float2half2_rn(v);
    return *reinterpret_cast<uint32_t*>(&h);
}
__device__ __forceinline__ uint32_t hmul2u(uint32_t a, uint32_t b) {
    __half2 r = __hmul2(*reinterpret_cast<__half2*>(&a), *reinterpret_cast<__half2*>(&b));
    return *reinterpret_cast<uint32_t*>(&r);
}
__device__ __forceinline__ uint32_t smem_u32(const void* p) {
    uint32_t a;
    asm("{ .reg .u64 t; cvta.to.shared.u64 t, %1; cvt.u32.u64 %0, t; }" : "=r"(a) : "l"(p));
    return a;
}
__device__ __forceinline__ void cpa16(uint32_t s, const void* g) {
    asm volatile("cp.async.cg.shared.global [%0], [%1], 16;" :: "r"(s), "l"(g));
}
#define CP_COMMIT() asm volatile("cp.async.commit_group;")
#define CP_WAIT2()  asm volatile("cp.async.wait_group 2;")

__device__ __forceinline__ void mma16(float (&d)[4], const uint32_t (&a)[4],
                                      uint32_t b0, uint32_t b1) {
    asm volatile(
        "mma.sync.aligned.m16n8k16.row.col.f32.f16.f16.f32 "
        "{%0,%1,%2,%3}, {%4,%5,%6,%7}, {%8,%9}, {%0,%1,%2,%3};"
        : "+f"(d[0]), "+f"(d[1]), "+f"(d[2]), "+f"(d[3])
        : "r"(a[0]), "r"(a[1]), "r"(a[2]), "r"(a[3]), "r"(b0), "r"(b1));
}

// ---------------------------------------------------------------------------
// Prep: gather w2/b2 into fp16 fragment-ordered chunks (identical to R10).
// ---------------------------------------------------------------------------
__global__ void prep_kernel(const float* __restrict__ w2, const float* __restrict__ b2) {
    int i = blockIdx.x * 256 + threadIdx.x;
    if (i < 51 * 1024) {                       // B1 (NT=8, N=64)
        int c = i >> 10, w = i & 1023;
        int p = w & 1, lane = (w >> 1) & 31, q = w >> 6;
        int s = q >> 3, nt = q & 7;
        int j = c / 17, k = c % 17;
        int kk = s * 16 + (lane & 3) * 2 + p * 8;
        int n  = nt * 8 + (lane >> 2);
        int col0 = (j < 2) ? ((j * 32 + kk) * 64 + n)     : (7168 + kk * 64 + n);
        int col1 = (j < 2) ? ((j * 32 + kk + 1) * 64 + n) : (7168 + (kk + 1) * 64 + n);
        float v0 = (k < 16) ? w2[k * WNUM + col0] : b2[col0];
        float v1 = (k < 16) ? w2[k * WNUM + col1] : b2[col1];
        g_B1[i] = pkh2(v0, v1);
        return;
    }
    i -= 51 * 1024;
    if (i < 34 * 512) {                        // B2 (NT=4, N=32)
        int c = i >> 9, w = i & 511;
        int p = w & 1, lane = (w >> 1) & 31, q = w >> 6;
        int s = q >> 2, nt = q & 3;
        int j = c / 17, k = c % 17;
        int kk = s * 16 + (lane & 3) * 2 + p * 8;
        int n  = nt * 8 + (lane >> 2);
        int col0 = 4096 + (j * 32 + kk) * 32 + n;
        int col1 = 4096 + (j * 32 + kk + 1) * 32 + n;
        float v0 = (k < 16) ? w2[k * WNUM + col0] : b2[col0];
        float v1 = (k < 16) ? w2[k * WNUM + col1] : b2[col1];
        g_B2[c * 512 + w] = pkh2(v0, v1);
        return;
    }
    i -= 34 * 512;
    if (i < 17 * 512) {                        // B3 (NT=4, N=32)
        int c = i >> 9, w = i & 511;
        int p = w & 1, lane = (w >> 1) & 31, q = w >> 6;
        int s = q >> 2, nt = q & 3;
        int k = c;
        int kk = s * 16 + (lane & 3) * 2 + p * 8;
        int n  = nt * 8 + (lane >> 2);
        int col0 = 6144 + kk * 32 + n;
        int col1 = 6144 + (kk + 1) * 32 + n;
        float v0 = (k < 16) ? w2[k * WNUM + col0] : b2[col0];
        float v1 = (k < 16) ? w2[k * WNUM + col1] : b2[col1];
        g_B3[c * 512 + w] = pkh2(v0, v1);
    }
}

// Chunk order: [0,34) Wa | [34,68) Wb | [68,85) Wd | [85,102) Wc
__device__ __forceinline__ const uint32_t* chunk_src(int c, int& nu) {
    if (c < 34) { nu = 1024; return g_B1 + c * 1024; }
    if (c < 68) { nu = 512;  return g_B2 + (c - 34) * 512; }
    if (c < 85) { nu = 1024; return g_B1 + (c - 34) * 1024; }
    nu = 512; return g_B3 + (c - 85) * 512;
}

// Slot map: slot -> (seg=slot/9, p=slot%9); c0=seg*17+2p, cnt=(p<8)?2:1. buf=slot&3.
__device__ __forceinline__ void stage_slot(int slot, uint32_t sbB, int t) {
    if (slot < NSLOT) {
        int seg = slot / 9;
        int p   = slot - seg * 9;
        int c0  = seg * 17 + 2 * p;
        int cnt = (p < 8) ? 2 : 1;
        uint32_t dst = sbB + (uint32_t)(slot & 3) * 8192u;
        int off = 0;
        for (int i = 0; i < cnt; i++) {
            int nu; const uint32_t* src = chunk_src(c0 + i, nu);
            int units = nu / 4;
            if (t < units) cpa16(dst + (uint32_t)(off + t * 4) * 4u, src + t * 4);
            off += nu;
        }
    }
    CP_COMMIT();
}

// One segment: 8 pairs + 1 single. NT = TOTAL n-tiles in chunk; each warp owns
// NT/2 tiles starting at nhalf*NT/2.
template<int NT>
__device__ __forceinline__ void run_seg(
    int slot0, const float* __restrict__ hb, float s00, float s01,
    const uint32_t* __restrict__ fbh,
    float (&acc)[NT/2][4],
    int eb, int lane, int nhalf, int t,
    const float* __restrict__ smemf, uint32_t sbB)
{
    const int NTL = NT / 2;
    const int r0 = lane >> 2;
    const int vp = lane & 3;
    uint32_t Ffh[2][4];
    #pragma unroll
    for (int s = 0; s < 2; s++) {
        int row = s * 8 + vp;
        Ffh[s][0] = fbh[row * 129 + eb + r0];
        Ffh[s][1] = fbh[row * 129 + eb + r0 + 8];
        Ffh[s][2] = fbh[(row + 4) * 129 + eb + r0];
        Ffh[s][3] = fbh[(row + 4) * 129 + eb + r0 + 8];
    }
    auto do_chunk = [&](int k, const uint2* __restrict__ Bb) {
        uint32_t h0 = h2bcast(hb[k * 128 + eb + r0] * s00);
        uint32_t h1 = h2bcast(hb[k * 128 + eb + r0 + 8] * s01);
        #pragma unroll
        for (int s = 0; s < 2; s++) {
            uint32_t a[4];
            a[0] = hmul2u(h0, Ffh[s][0]);
            a[1] = hmul2u(h1, Ffh[s][1]);
            a[2] = hmul2u(h0, Ffh[s][2]);
            a[3] = hmul2u(h1, Ffh[s][3]);
            #pragma unroll
            for (int ntl = 0; ntl < NTL; ntl++) {
                uint2 bv = Bb[(s * NT + nhalf * NTL + ntl) * 32 + lane];
                mma16(acc[ntl], a, bv.x, bv.y);
            }
        }
    };
    #pragma unroll 1
    for (int p = 0; p < 8; p++) {
        int s = slot0 + p;
        CP_WAIT2();
        __syncthreads();
        stage_slot(s + 3, sbB, t);
        const float* bbase = smemf + OFF_BB + (size_t)((s & 3) * 2048);
        do_chunk(2 * p,     (const uint2*)bbase);
        do_chunk(2 * p + 1, (const uint2*)(bbase + NT * 128));
    }
    {
        int s = slot0 + 8;
        CP_WAIT2();
        __syncthreads();
        stage_slot(s + 3, sbB, t);
        do_chunk(16, (const uint2*)(smemf + OFF_BB + (size_t)((s & 3) * 2048)));
    }
}

__device__ __forceinline__ void run_seg3(
    int slot0, const float* __restrict__ hb,
    const uint32_t* __restrict__ xch,      // [3][16][129] half2-words
    float (&pc)[3][2][4],
    int eb, int lane, int nhalf, int t,
    const float* __restrict__ smemf, uint32_t sbB)
{
    const int r0 = lane >> 2;
    const int vp = lane & 3;
    uint32_t Ffh[3][2][4];
    #pragma unroll
    for (int m = 0; m < 3; m++) {
        const uint32_t* fbh = xch + m * 2064;
        #pragma unroll
        for (int s = 0; s < 2; s++) {
            int row = s * 8 + vp;
            Ffh[m][s][0] = fbh[row * 129 + eb + r0];
            Ffh[m][s][1] = fbh[row * 129 + eb + r0 + 8];
            Ffh[m][s][2] = fbh[(row + 4) * 129 + eb + r0];
            Ffh[m][s][3] = fbh[(row + 4) * 129 + eb + r0 + 8];
        }
    }
    auto do_chunk = [&](int k, const uint2* __restrict__ Bb) {
        uint32_t h0 = h2bcast(hb[k * 128 + eb + r0]);
        uint32_t h1 = h2bcast(hb[k * 128 + eb + r0 + 8]);
        #pragma unroll
        for (int s = 0; s < 2; s++) {
            uint32_t a[3][4];
            #pragma unroll
            for (int m = 0; m < 3; m++) {
                a[m][0] = hmul2u(h0, Ffh[m][s][0]);
                a[m][1] = hmul2u(h1, Ffh[m][s][1]);
                a[m][2] = hmul2u(h0, Ffh[m][s][2]);
                a[m][3] = hmul2u(h1, Ffh[m][s][3]);
            }
            #pragma unroll
            for (int ntl = 0; ntl < 2; ntl++) {
                uint2 bv = Bb[(s * 4 + nhalf * 2 + ntl) * 32 + lane];
                #pragma unroll
                for (int m = 0; m < 3; m++)
                    mma16(pc[m][ntl], a[m], bv.x, bv.y);
            }
        }
    };
    #pragma unroll 1
    for (int p = 0; p < 8; p++) {
        int s = slot0 + p;
        CP_WAIT2();
        __syncthreads();
        stage_slot(s + 3, sbB, t);
        const float* bbase = smemf + OFF_BB + (size_t)((s & 3) * 2048);
        do_chunk(2 * p,     (const uint2*)bbase);
        do_chunk(2 * p + 1, (const uint2*)(bbase + 512));
    }
    {
        int s = slot0 + 8;
        CP_WAIT2();
        __syncthreads();
        stage_slot(s + 3, sbB, t);
        do_chunk(16, (const uint2*)(smemf + OFF_BB + (size_t)((s & 3) * 2048)));
    }
}

extern __shared__ float smem[];

__global__ void __launch_bounds__(NTHR, 2) conv_mma_kernel(
    const float* __restrict__ x,    const float* __restrict__ rps,
    const float* __restrict__ dist, const float* __restrict__ freq,
    const float* __restrict__ w1,   const float* __restrict__ b1,
    float* __restrict__ out)
{
    const int t     = threadIdx.x;
    const int wid   = t >> 5;
    const int lane  = t & 31;
    const int nhalf = wid >> 3;          // which N-half this warp owns
    const int eb    = (wid & 7) * 16;    // 16-edge strip
    const int e0    = blockIdx.x * EB;
    const uint32_t sbB = smem_u32(smem) + OFF_BB * 4;

    uint32_t* X0Hw = (uint32_t*)(smem + OFF_X0H);
    uint32_t* XCHw = (uint32_t*)(smem + OFF_XCH);
    uint32_t* ZADw = (uint32_t*)(smem + OFF_ZADH);
    __half*   xchh = (__half*)XCHw;

    // prologue: stage slots 0,1,2 — overlaps setup
    stage_slot(0, sbB, t);
    stage_slot(1, sbB, t);
    stage_slot(2, sbB, t);

    // --- setup: radial MLP + sh ---
    if (t < EB) {
        int e = e0 + t;
        if (e < E_TOT) {
            float d  = dist[e] * 0.25f;
            float id = 1.0f / d;
            float d2 = d * d;
            float d5 = d2 * d2 * d;
            float env = id - 28.0f * d5 + 48.0f * d5 * d - 21.0f * d5 * d2;
            env = (d < 1.0f) ? env : 0.0f;
            float basis[NB];
            #pragma unroll
            for (int i = 0; i < NB; i++) basis[i] = env * sinf(freq[i] * d);
            float s0 = rps[e * 4 + 0];
            smem[OFF_SH0 + t]           = s0;
            smem[OFF_SH1 + 0 * 128 + t] = rps[e * 4 + 1];
            smem[OFF_SH1 + 1 * 128 + t] = rps[e * 4 + 2];
            smem[OFF_SH1 + 2 * 128 + t] = rps[e * 4 + 3];
            #pragma unroll
            for (int k = 0; k < 16; k++) {
                float pre = b1[k];
                #pragma unroll
                for (int i = 0; i < NB; i++) pre = fmaf(basis[i], w1[i * 16 + k], pre);
                float sg = 1.0f / (1.0f + expf(-pre));
                smem[OFF_H + k * 128 + t] = pre * sg;
            }
            smem[OFF_H + 16 * 128 + t] = 1.0f;
        } else {
            #pragma unroll
            for (int k = 0; k < 17; k++) smem[OFF_H + k * 128 + t] = 0.0f;
            smem[OFF_SH0 + t] = 0.0f;
            smem[OFF_SH1 + 0 * 128 + t] = 0.0f;
            smem[OFF_SH1 + 1 * 128 + t] = 0.0f;
            smem[OFF_SH1 + 2 * 128 + t] = 0.0f;
        }
    }

    // --- x tiles -> half2 arrays (v-pair packed, stride 129 words) ---
    for (int idx = t; idx < EB * 40; idx += NTHR) {
        int el = idx / 40, c4 = idx - el * 40;
        int e  = e0 + el;
        float4 v = make_float4(0.f, 0.f, 0.f, 0.f);
        if (e < E_TOT) v = *(const float4*)&x[(size_t)e * 160 + c4 * 4];
        if (c4 < 16) {
            int pr = c4 * 2;
            X0Hw[(pr + 0) * 129 + el] = pkh2(v.x, v.y);
            X0Hw[(pr + 1) * 129 + el] = pkh2(v.z, v.w);
        } else {
            int q0 = c4 * 4 - 64;
            float vv[4] = {v.x, v.y, v.z, v.w};
            #pragma unroll
            for (int j = 0; j < 4; j++) {
                int q = q0 + j;
                int u = q / 3, m = q - 3 * u;
                xchh[(m * 2064 + (u >> 1) * 129 + el) * 2 + (u & 1)] = __float2half(vv[j]);
            }
        }
    }
    __syncthreads();

    const float* H = smem + OFF_H;
    const float s00 = smem[OFF_SH0 + eb + (lane >> 2)];
    const float s01 = smem[OFF_SH0 + eb + (lane >> 2) + 8];

    // --- phase 1a/1b: Wa on x0 (A = h*sh0*x0) ---
    float acc1[4][4];
    #pragma unroll
    for (int i = 0; i < 4; i++) { acc1[i][0]=acc1[i][1]=acc1[i][2]=acc1[i][3]=0.f; }
    run_seg<8>(0, H, s00, s01, X0Hw, acc1, eb, lane, nhalf, t, smem, sbB);
    run_seg<8>(9, H, s00, s01, X0Hw + 16 * 129, acc1, eb, lane, nhalf, t, smem, sbB);

    // --- phase 2: Wb on x0 (A = h*x0) -> pb ---
    float acc2[2][4];
    #pragma unroll
    for (int i = 0; i < 2; i++) { acc2[i][0]=acc2[i][1]=acc2[i][2]=acc2[i][3]=0.f; }
    run_seg<4>(18, H, 1.0f, 1.0f, X0Hw, acc2, eb, lane, nhalf, t, smem, sbB);
    run_seg<4>(27, H, 1.0f, 1.0f, X0Hw + 16 * 129, acc2, eb, lane, nhalf, t, smem, sbB);

    // --- build zAd (own region), then stash pb over X0H ---
    __syncthreads();
    for (int idx = t; idx < 16 * 128; idx += NTHR) {
        int up = idx >> 7, el = idx & 127;
        float a0 = 0.f, a1 = 0.f;
        #pragma unroll
        for (int m = 0; m < 3; m++) {
            uint32_t w = XCHw[m * 2064 + up * 129 + el];
            float2 f = __half22float2(*reinterpret_cast<__half2*>(&w));
            float sv = smem[OFF_SH1 + m * 128 + el];
            a0 = fmaf(f.x, sv, a0);
            a1 = fmaf(f.y, sv, a1);
        }
        ZADw[up * 129 + el] = pkh2(a0 * INV_S3, a1 * INV_S3);
    }
    __syncthreads();
    {
        const int r0 = lane >> 2, cpair = 2 * (lane & 3);
        float* pbS = smem + OFF_PB;
        #pragma unroll
        for (int nt = 0; nt < 2; nt++) {
            int w0 = (nhalf * 2 + nt) * 8 + cpair;
            pbS[(w0 + 0) * 129 + eb + r0]     = acc2[nt][0];
            pbS[(w0 + 1) * 129 + eb + r0]     = acc2[nt][1];
            pbS[(w0 + 0) * 129 + eb + r0 + 8] = acc2[nt][2];
            pbS[(w0 + 1) * 129 + eb + r0 + 8] = acc2[nt][3];
        }
    }

    // --- phase 1c: Wd on zAd ---
    run_seg<8>(36, H, 1.0f, 1.0f, ZADw, acc1, eb, lane, nhalf, t, smem, sbB);

    // out0 epilogue
    const int r0 = lane >> 2, cpair = 2 * (lane & 3);
    #pragma unroll
    for (int nt = 0; nt < 4; nt++) {
        int col = (nhalf * 4 + nt) * 8 + cpair;
        int eA = e0 + eb + r0;
        if (eA < E_TOT)
            *(float2*)&out[(size_t)eA * 160 + col] =
                make_float2(PW0 * acc1[nt][0], PW0 * acc1[nt][1]);
        int eB = eA + 8;
        if (eB < E_TOT)
            *(float2*)&out[(size_t)eB * 160 + col] =
                make_float2(PW0 * acc1[nt][2], PW0 * acc1[nt][3]);
    }

    // --- phase 3: Wc on xc -> pc ---
    float pcx[3][2][4];
    #pragma unroll
    for (int m = 0; m < 3; m++)
        #pragma unroll
        for (int i = 0; i < 2; i++) { pcx[m][i][0]=pcx[m][i][1]=pcx[m][i][2]=pcx[m][i][3]=0.f; }
    run_seg3(45, H, XCHw, pcx, eb, lane, nhalf, t, smem, sbB);

    // --- out1 epilogue (sync so pb stash is visible across warps) ---
    __syncthreads();
    const float* pbS = smem + OFF_PB;
    #pragma unroll
    for (int ntl = 0; ntl < 2; ntl++) {
        int w0 = (nhalf * 2 + ntl) * 8 + cpair;
        #pragma unroll
        for (int half = 0; half < 2; half++) {
            int el = eb + r0 + half * 8;
            int e  = e0 + el;
            if (e >= E_TOT) continue;
            float s0v = smem[OFF_SH0 + el];
            float s1v[3];
            #pragma unroll
            for (int m = 0; m < 3; m++) s1v[m] = smem[OFF_SH1 + m * 128 + el];
            float pb0 = pbS[(w0 + 0) * 129 + el];
            float pb1 = pbS[(w0 + 1) * 129 + el];
            float vals[6];
            #pragma unroll
            for (int m = 0; m < 3; m++) {
                vals[m]     = PW1S * (pb0 * s1v[m] + pcx[m][ntl][half * 2 + 0] * s0v);
                vals[3 + m] = PW1S * (pb1 * s1v[m] + pcx[m][ntl][half * 2 + 1] * s0v);
            }
            size_t base = (size_t)e * 160 + 64 + 3 * w0;
            *(float2*)&out[base + 0] = make_float2(vals[0], vals[1]);
            *(float2*)&out[base + 2] = make_float2(vals[2], vals[3]);
            *(float2*)&out[base + 4] = make_float2(vals[4], vals[5]);
        }
    }
}

extern "C" void kernel_launch(void* const* d_in, const int* in_sizes, int n_in,
                              void* d_out, int out_size) {
    (void)in_sizes; (void)n_in; (void)out_size;
    const float* x    = (const float*)d_in[0];
    const float* rps  = (const float*)d_in[1];
    const float* dist = (const float*)d_in[2];
    const float* freq = (const float*)d_in[3];
    const float* w1   = (const float*)d_in[4];
    const float* b1   = (const float*)d_in[5];
    const float* w2   = (const float*)d_in[6];
    const float* b2   = (const float*)d_in[7];
    float* out = (float*)d_out;

    const int tot = 51 * 1024 + 34 * 512 + 17 * 512;
    prep_kernel<<<(tot + 255) / 256, 256>>>(w2, b2);

    cudaFuncSetAttribute(conv_mma_kernel,
                         cudaFuncAttributeMaxDynamicSharedMemorySize, SMEM_BYTES);
    const int nblocks = (E_TOT + EB - 1) / EB;   // 235
    conv_mma_kernel<<<nblocks, NTHR, SMEM_BYTES>>>(x, rps, dist, freq, w1, b1, out);
}

// round 15
// speedup vs baseline: 1.2555x; 1.2555x over previous
#include <cuda_runtime.h>
#include <cuda_fp16.h>
#include <cstdint>

#define E_TOT   30000
#define NB      10
#define WNUM    9216
#define EB      128
#define NTHR    256
#define INV_S3  0.5773502691896258f
#define PW0     0.10206207261596575f
#define PW1     0.17677669529663687f
#define PW1S    (PW1 * INV_S3)

// Packed half2 B fragments (u32 each), fragment-ordered per chunk (same as R10).
__device__ uint32_t g_B1[51 * 1024];   // N=64 chunks: Wa j0 (0-16), Wa j1 (17-33), Wd (34-50)
__device__ uint32_t g_B2[34 * 512];    // N=32 chunks: Wb j0 (0-16), Wb j1 (17-33)
__device__ uint32_t g_B3[17 * 512];    // N=32 chunks: Wc

// SMEM word offsets (15072 words = 58.9 KB -> 2 CTAs/SM, ~110 KB L1D left)
#define OFF_H    0        // [17][128] f32
#define OFF_X0H  2176     // [32 vpair][129] half2-words (PB f32 overlay after Wb)
#define OFF_PB   OFF_X0H  // [32][129] f32
#define OFF_XCH  6304     // [3 m][16 upair][129] half2-words
#define OFF_ZADH 12496    // [16 upair][129] half2-words
#define OFF_SH0  14560    // [128]
#define OFF_SH1  14688    // [3][128]
#define SMEM_FL  15072
#define SMEM_BYTES (SMEM_FL * 4)

__device__ __forceinline__ uint32_t pkh2(float lo, float hi) {
    __half2 h = __floats2half2_rn(lo, hi);
    return *reinterpret_cast<uint32_t*>(&h);
}
__device__ __forceinline__ uint32_t h2bcast(float v) {
    __half2 h = __float2half2_rn(v);
    return *reinterpret_cast<uint32_t*>(&h);
}
__device__ __forceinline__ uint32_t hmul2u(uint32_t a, uint32_t b) {
    __half2 r = __hmul2(*reinterpret_cast<__half2*>(&a), *reinterpret_cast<__half2*>(&b));
    return *reinterpret_cast<uint32_t*>(&r);
}

__device__ __forceinline__ void mma16(float (&d)[4], const uint32_t (&a)[4],
                                      uint32_t b0, uint32_t b1) {
    asm volatile(
        "mma.sync.aligned.m16n8k16.row.col.f32.f16.f16.f32 "
        "{%0,%1,%2,%3}, {%4,%5,%6,%7}, {%8,%9}, {%0,%1,%2,%3};"
        : "+f"(d[0]), "+f"(d[1]), "+f"(d[2]), "+f"(d[3])
        : "r"(a[0]), "r"(a[1]), "r"(a[2]), "r"(a[3]), "r"(b0), "r"(b1));
}

// ---------------------------------------------------------------------------
// Prep: gather w2/b2 into fp16 fragment-ordered chunks (identical to R10).
// u32 index within chunk = ((s*NT + nt)*32 + lane)*2 + p
//   kk = s*16 + (lane&3)*2 + p*8 (+0/+1 lo/hi half);  n = nt*8 + (lane>>2)
// ---------------------------------------------------------------------------
__global__ void prep_kernel(const float* __restrict__ w2, const float* __restrict__ b2) {
    int i = blockIdx.x * 256 + threadIdx.x;
    if (i < 51 * 1024) {                       // B1 (NT=8, N=64)
        int c = i >> 10, w = i & 1023;
        int p = w & 1, lane = (w >> 1) & 31, q = w >> 6;
        int s = q >> 3, nt = q & 7;
        int j = c / 17, k = c % 17;
        int kk = s * 16 + (lane & 3) * 2 + p * 8;
        int n  = nt * 8 + (lane >> 2);
        int col0 = (j < 2) ? ((j * 32 + kk) * 64 + n)     : (7168 + kk * 64 + n);
        int col1 = (j < 2) ? ((j * 32 + kk + 1) * 64 + n) : (7168 + (kk + 1) * 64 + n);
        float v0 = (k < 16) ? w2[k * WNUM + col0] : b2[col0];
        float v1 = (k < 16) ? w2[k * WNUM + col1] : b2[col1];
        g_B1[i] = pkh2(v0, v1);
        return;
    }
    i -= 51 * 1024;
    if (i < 34 * 512) {                        // B2 (NT=4, N=32)
        int c = i >> 9, w = i & 511;
        int p = w & 1, lane = (w >> 1) & 31, q = w >> 6;
        int s = q >> 2, nt = q & 3;
        int j = c / 17, k = c % 17;
        int kk = s * 16 + (lane & 3) * 2 + p * 8;
        int n  = nt * 8 + (lane >> 2);
        int col0 = 4096 + (j * 32 + kk) * 32 + n;
        int col1 = 4096 + (j * 32 + kk + 1) * 32 + n;
        float v0 = (k < 16) ? w2[k * WNUM + col0] : b2[col0];
        float v1 = (k < 16) ? w2[k * WNUM + col1] : b2[col1];
        g_B2[c * 512 + w] = pkh2(v0, v1);
        return;
    }
    i -= 34 * 512;
    if (i < 17 * 512) {                        // B3 (NT=4, N=32)
        int c = i >> 9, w = i & 511;
        int p = w & 1, lane = (w >> 1) & 31, q = w >> 6;
        int s = q >> 2, nt = q & 3;
        int k = c;
        int kk = s * 16 + (lane & 3) * 2 + p * 8;
        int n  = nt * 8 + (lane >> 2);
        int col0 = 6144 + kk * 32 + n;
        int col1 = 6144 + (kk + 1) * 32 + n;
        float v0 = (k < 16) ? w2[k * WNUM + col0] : b2[col0];
        float v1 = (k < 16) ? w2[k * WNUM + col1] : b2[col1];
        g_B3[c * 512 + w] = pkh2(v0, v1);
    }
}

// One 17-chunk segment, B streamed straight from global via __ldg.
// Bseg points at the segment's first chunk; per-chunk stride = NT*64 uint2.
template<int NT>
__device__ __forceinline__ void run_seg(
    const uint2* __restrict__ Bseg,
    const float* __restrict__ hb, float s00, float s01,
    const uint32_t* __restrict__ fbh,
    float (&acc)[NT][4],
    int eb, int lane)
{
    const int r0 = lane >> 2;
    const int vp = lane & 3;
    uint32_t Ffh[2][4];
    #pragma unroll
    for (int s = 0; s < 2; s++) {
        int row = s * 8 + vp;
        Ffh[s][0] = fbh[row * 129 + eb + r0];
        Ffh[s][1] = fbh[row * 129 + eb + r0 + 8];
        Ffh[s][2] = fbh[(row + 4) * 129 + eb + r0];
        Ffh[s][3] = fbh[(row + 4) * 129 + eb + r0 + 8];
    }
    #pragma unroll 1
    for (int k = 0; k < 17; k++) {
        const uint2* Bb = Bseg + (size_t)k * (NT * 64);
        uint32_t h0 = h2bcast(hb[k * 128 + eb + r0] * s00);
        uint32_t h1 = h2bcast(hb[k * 128 + eb + r0 + 8] * s01);
        #pragma unroll
        for (int s = 0; s < 2; s++) {
            uint32_t a[4];
            a[0] = hmul2u(h0, Ffh[s][0]);
            a[1] = hmul2u(h1, Ffh[s][1]);
            a[2] = hmul2u(h0, Ffh[s][2]);
            a[3] = hmul2u(h1, Ffh[s][3]);
            #pragma unroll
            for (int nt = 0; nt < NT; nt++) {
                uint2 bv = __ldg(&Bb[(s * NT + nt) * 32 + lane]);
                mma16(acc[nt], a, bv.x, bv.y);
            }
        }
    }
}

__device__ __forceinline__ void run_seg3(
    const uint2* __restrict__ Bseg,
    const float* __restrict__ hb,
    const uint32_t* __restrict__ xch,      // [3][16][129] half2-words
    float (&pc)[3][4][4],
    int eb, int lane)
{
    const int r0 = lane >> 2;
    const int vp = lane & 3;
    uint32_t Ffh[3][2][4];
    #pragma unroll
    for (int m = 0; m < 3; m++) {
        const uint32_t* fbh = xch + m * 2064;
        #pragma unroll
        for (int s = 0; s < 2; s++) {
            int row = s * 8 + vp;
            Ffh[m][s][0] = fbh[row * 129 + eb + r0];
            Ffh[m][s][1] = fbh[row * 129 + eb + r0 + 8];
            Ffh[m][s][2] = fbh[(row + 4) * 129 + eb + r0];
            Ffh[m][s][3] = fbh[(row + 4) * 129 + eb + r0 + 8];
        }
    }
    #pragma unroll 1
    for (int k = 0; k < 17; k++) {
        const uint2* Bb = Bseg + (size_t)k * 256;
        uint32_t h0 = h2bcast(hb[k * 128 + eb + r0]);
        uint32_t h1 = h2bcast(hb[k * 128 + eb + r0 + 8]);
        #pragma unroll
        for (int s = 0; s < 2; s++) {
            uint32_t a[3][4];
            #pragma unroll
            for (int m = 0; m < 3; m++) {
                a[m][0] = hmul2u(h0, Ffh[m][s][0]);
                a[m][1] = hmul2u(h1, Ffh[m][s][1]);
                a[m][2] = hmul2u(h0, Ffh[m][s][2]);
                a[m][3] = hmul2u(h1, Ffh[m][s][3]);
            }
            #pragma unroll
            for (int nt = 0; nt < 4; nt++) {
                uint2 bv = __ldg(&Bb[(s * 4 + nt) * 32 + lane]);
                #pragma unroll
                for (int m = 0; m < 3; m++)
                    mma16(pc[m][nt], a[m], bv.x, bv.y);
            }
        }
    }
}

extern __shared__ float smem[];

__global__ void __launch_bounds__(NTHR, 2) conv_mma_kernel(
    const float* __restrict__ x,    const float* __restrict__ rps,
    const float* __restrict__ dist, const float* __restrict__ freq,
    const float* __restrict__ w1,   const float* __restrict__ b1,
    float* __restrict__ out)
{
    const int t    = threadIdx.x;
    const int lane = t & 31;
    const int eb   = (t >> 5) * 16;
    const int e0   = blockIdx.x * EB;

    uint32_t* X0Hw = (uint32_t*)(smem + OFF_X0H);
    uint32_t* XCHw = (uint32_t*)(smem + OFF_XCH);
    uint32_t* ZADw = (uint32_t*)(smem + OFF_ZADH);
    __half*   xchh = (__half*)XCHw;

    // --- setup: radial MLP + sh ---
    if (t < EB) {
        int e = e0 + t;
        if (e < E_TOT) {
            float d  = dist[e] * 0.25f;
            float id = 1.0f / d;
            float d2 = d * d;
            float d5 = d2 * d2 * d;
            float env = id - 28.0f * d5 + 48.0f * d5 * d - 21.0f * d5 * d2;
            env = (d < 1.0f) ? env : 0.0f;
            float basis[NB];
            #pragma unroll
            for (int i = 0; i < NB; i++) basis[i] = env * sinf(freq[i] * d);
            float s0 = rps[e * 4 + 0];
            smem[OFF_SH0 + t]           = s0;
            smem[OFF_SH1 + 0 * 128 + t] = rps[e * 4 + 1];
            smem[OFF_SH1 + 1 * 128 + t] = rps[e * 4 + 2];
            smem[OFF_SH1 + 2 * 128 + t] = rps[e * 4 + 3];
            #pragma unroll
            for (int k = 0; k < 16; k++) {
                float pre = b1[k];
                #pragma unroll
                for (int i = 0; i < NB; i++) pre = fmaf(basis[i], w1[i * 16 + k], pre);
                float sg = 1.0f / (1.0f + expf(-pre));
                smem[OFF_H + k * 128 + t] = pre * sg;
            }
            smem[OFF_H + 16 * 128 + t] = 1.0f;
        } else {
            #pragma unroll
            for (int k = 0; k < 17; k++) smem[OFF_H + k * 128 + t] = 0.0f;
            smem[OFF_SH0 + t] = 0.0f;
            smem[OFF_SH1 + 0 * 128 + t] = 0.0f;
            smem[OFF_SH1 + 1 * 128 + t] = 0.0f;
            smem[OFF_SH1 + 2 * 128 + t] = 0.0f;
        }
    }

    // --- x tiles -> half2 arrays (v-pair packed, stride 129 words) ---
    for (int idx = t; idx < EB * 40; idx += NTHR) {
        int el = idx / 40, c4 = idx - el * 40;
        int e  = e0 + el;
        float4 v = make_float4(0.f, 0.f, 0.f, 0.f);
        if (e < E_TOT) v = *(const float4*)&x[(size_t)e * 160 + c4 * 4];
        if (c4 < 16) {
            int pr = c4 * 2;
            X0Hw[(pr + 0) * 129 + el] = pkh2(v.x, v.y);
            X0Hw[(pr + 1) * 129 + el] = pkh2(v.z, v.w);
        } else {
            int q0 = c4 * 4 - 64;
            float vv[4] = {v.x, v.y, v.z, v.w};
            #pragma unroll
            for (int j = 0; j < 4; j++) {
                int q = q0 + j;
                int u = q / 3, m = q - 3 * u;
                xchh[(m * 2064 + (u >> 1) * 129 + el) * 2 + (u & 1)] = __float2half(vv[j]);
            }
        }
    }
    __syncthreads();

    const float* H = smem + OFF_H;
    const float s00 = smem[OFF_SH0 + eb + (lane >> 2)];
    const float s01 = smem[OFF_SH0 + eb + (lane >> 2) + 8];

    const uint2* B1p = (const uint2*)g_B1;
    const uint2* B2p = (const uint2*)g_B2;
    const uint2* B3p = (const uint2*)g_B3;

    // --- phase 1a/1b: Wa on x0 (A = h*sh0*x0) ---
    float acc1[8][4];
    #pragma unroll
    for (int i = 0; i < 8; i++) { acc1[i][0]=acc1[i][1]=acc1[i][2]=acc1[i][3]=0.f; }
    run_seg<8>(B1p,              H, s00, s01, X0Hw,            acc1, eb, lane);
    __syncthreads();
    run_seg<8>(B1p + 17 * 512,   H, s00, s01, X0Hw + 16 * 129, acc1, eb, lane);
    __syncthreads();

    // --- phase 2: Wb on x0 (A = h*x0) -> pb ---
    float acc2[4][4];
    #pragma unroll
    for (int i = 0; i < 4; i++) { acc2[i][0]=acc2[i][1]=acc2[i][2]=acc2[i][3]=0.f; }
    run_seg<4>(B2p,              H, 1.0f, 1.0f, X0Hw,            acc2, eb, lane);
    __syncthreads();
    run_seg<4>(B2p + 17 * 256,   H, 1.0f, 1.0f, X0Hw + 16 * 129, acc2, eb, lane);

    // --- build zAd (own region), then stash pb over X0H ---
    __syncthreads();
    for (int idx = t; idx < 16 * 128; idx += NTHR) {
        int up = idx >> 7, el = idx & 127;
        float a0 = 0.f, a1 = 0.f;
        #pragma unroll
        for (int m = 0; m < 3; m++) {
            uint32_t w = XCHw[m * 2064 + up * 129 + el];
            float2 f = __half22float2(*reinterpret_cast<__half2*>(&w));
            float sv = smem[OFF_SH1 + m * 128 + el];
            a0 = fmaf(f.x, sv, a0);
            a1 = fmaf(f.y, sv, a1);
        }
        ZADw[up * 129 + el] = pkh2(a0 * INV_S3, a1 * INV_S3);
    }
    __syncthreads();
    {
        const int r0 = lane >> 2, cpair = 2 * (lane & 3);
        float* pbS = smem + OFF_PB;
        #pragma unroll
        for (int nt = 0; nt < 4; nt++) {
            int w0 = nt * 8 + cpair;
            pbS[(w0 + 0) * 129 + eb + r0]     = acc2[nt][0];
            pbS[(w0 + 1) * 129 + eb + r0]     = acc2[nt][1];
            pbS[(w0 + 0) * 129 + eb + r0 + 8] = acc2[nt][2];
            pbS[(w0 + 1) * 129 + eb + r0 + 8] = acc2[nt][3];
        }
    }

    // --- phase 1c: Wd on zAd ---
    run_seg<8>(B1p + 34 * 512, H, 1.0f, 1.0f, ZADw, acc1, eb, lane);

    // out0 epilogue
    const int r0 = lane >> 2, cpair = 2 * (lane & 3);
    #pragma unroll
    for (int nt = 0; nt < 8; nt++) {
        int col = nt * 8 + cpair;
        int eA = e0 + eb + r0;
        if (eA < E_TOT)
            *(float2*)&out[(size_t)eA * 160 + col] =
                make_float2(PW0 * acc1[nt][0], PW0 * acc1[nt][1]);
        int eB = eA + 8;
        if (eB < E_TOT)
            *(float2*)&out[(size_t)eB * 160 + col] =
                make_float2(PW0 * acc1[nt][2], PW0 * acc1[nt][3]);
    }

    // --- phase 3: Wc on xc -> pc ---
    __syncthreads();
    float pcx[3][4][4];
    #pragma unroll
    for (int m = 0; m < 3; m++)
        #pragma unroll
        for (int i = 0; i < 4; i++) { pcx[m][i][0]=pcx[m][i][1]=pcx[m][i][2]=pcx[m][i][3]=0.f; }
    run_seg3(B3p, H, XCHw, pcx, eb, lane);

    // --- out1 epilogue ---
    const float* pbS = smem + OFF_PB;
    #pragma unroll
    for (int nt = 0; nt < 4; nt++) {
        int w0 = nt * 8 + cpair;
        #pragma unroll
        for (int half = 0; half < 2; half++) {
            int el = eb + r0 + half * 8;
            int e  = e0 + el;
            if (e >= E_TOT) continue;
            float s0v = smem[OFF_SH0 + el];
            float s1v[3];
            #pragma unroll
            for (int m = 0; m < 3; m++) s1v[m] = smem[OFF_SH1 + m * 128 + el];
            float pb0 = pbS[(w0 + 0) * 129 + el];
            float pb1 = pbS[(w0 + 1) * 129 + el];
            float vals[6];
            #pragma unroll
            for (int m = 0; m < 3; m++) {
                vals[m]     = PW1S * (pb0 * s1v[m] + pcx[m][nt][half * 2 + 0] * s0v);
                vals[3 + m] = PW1S * (pb1 * s1v[m] + pcx[m][nt][half * 2 + 1] * s0v);
            }
            size_t base = (size_t)e * 160 + 64 + 3 * w0;
            *(float2*)&out[base + 0] = make_float2(vals[0], vals[1]);
            *(float2*)&out[base + 2] = make_float2(vals[2], vals[3]);
            *(float2*)&out[base + 4] = make_float2(vals[4], vals[5]);
        }
    }
}

extern "C" void kernel_launch(void* const* d_in, const int* in_sizes, int n_in,
                              void* d_out, int out_size) {
    (void)in_sizes; (void)n_in; (void)out_size;
    const float* x    = (const float*)d_in[0];
    const float* rps  = (const float*)d_in[1];
    const float* dist = (const float*)d_in[2];
    const float* freq = (const float*)d_in[3];
    const float* w1   = (const float*)d_in[4];
    const float* b1   = (const float*)d_in[5];
    const float* w2   = (const float*)d_in[6];
    const float* b2   = (const float*)d_in[7];
    float* out = (float*)d_out;

    const int tot = 51 * 1024 + 34 * 512 + 17 * 512;
    prep_kernel<<<(tot + 255) / 256, 256>>>(w2, b2);

    cudaFuncSetAttribute(conv_mma_kernel,
                         cudaFuncAttributeMaxDynamicSharedMemorySize, SMEM_BYTES);
    const int nblocks = (E_TOT + EB - 1) / EB;   // 235
    conv_mma_kernel<<<nblocks, NTHR, SMEM_BYTES>>>(x, rps, dist, freq, w1, b1, out);
}